// round 2
// baseline (speedup 1.0000x reference)
#include <cuda_runtime.h>
#include <math.h>

#define TT 8192
#define HH 2048
#define II 8192

// Static device scratch (allocation-free rule: __device__ globals are the sanctioned path)
__device__ float g_xk[TT * HH];                 //  64 MB
__device__ float g_xr[TT * HH];                 //  64 MB
__device__ float g_k [(size_t)TT * II];         // 256 MB
__device__ float g_s [TT * HH];                 //  64 MB

// ---------------------------------------------------------------------------
// Token shift + time-mix:  xk = x*mk + state*(1-mk),  xr = x*mr + state*(1-mr)
// state[t] = (pos[t]==0) ? 0 : x[t-1]
// ---------------------------------------------------------------------------
__global__ void shift_kernel(const float* __restrict__ x,
                             const int*   __restrict__ pos,
                             const float* __restrict__ tmk,
                             const float* __restrict__ tmr) {
    int idx = blockIdx.x * blockDim.x + threadIdx.x;
    if (idx >= TT * HH) return;
    int t = idx >> 11;            // / HH (HH = 2048)
    int h = idx & (HH - 1);
    float xv = x[idx];
    float st = (pos[t] == 0) ? 0.0f : x[idx - HH];
    float mk = tmk[h];
    float mr = tmr[h];
    g_xk[idx] = xv * mk + st * (1.0f - mk);
    g_xr[idx] = xv * mr + st * (1.0f - mr);
}

// ---------------------------------------------------------------------------
// SGEMM: C[M,N] = epilogue(A[M,K] @ B[K,N] + bias)
//   EPI 0: relu(c)^2
//   EPI 1: sigmoid(c)
//   EPI 2: c * aux[row,col]
// Tiles: BM=BN=128, BK=16; 256 threads; 8x8 per-thread micro-tile.
// All problem dims divide tile dims evenly -> no bounds checks.
// Grid swizzle: group 8 M-tiles per column-sweep for L2 panel reuse.
// ---------------------------------------------------------------------------
template <int EPI>
__global__ __launch_bounds__(256, 2)
void sgemm_kernel(const float* __restrict__ A,
                  const float* __restrict__ B,
                  const float* __restrict__ bias,
                  const float* __restrict__ aux,
                  float* __restrict__ C,
                  int M, int N, int K) {
    constexpr int BM = 128, BN = 128, BK = 16;
    constexpr int BMP = BM + 4;   // pad: keeps 16B alignment (132 % 4 == 0)

    __shared__ float As[BK][BMP];  // transposed A tile
    __shared__ float Bs[BK][BN];

    const int tid = threadIdx.x;
    const int tm  = tid >> 4;      // 0..15
    const int tn  = tid & 15;      // 0..15

    // ---- grid swizzle: linearize then re-tile with GROUP_M m-tiles per band ----
    const int mtiles = M / BM;
    const int ntiles = N / BN;
    const int lin    = blockIdx.y * gridDim.x + blockIdx.x;
    constexpr int GROUP_M = 8;
    const int band       = lin / (GROUP_M * ntiles);          // which m-band
    const int in_band    = lin % (GROUP_M * ntiles);
    const int band_rows  = min(GROUP_M, mtiles - band * GROUP_M);
    const int bm         = band * GROUP_M + (in_band % band_rows);
    const int bn         = in_band / band_rows;

    const float* Ablk = A + (size_t)bm * BM * K;
    const float* Bblk = B + (size_t)bn * BN;

    float acc[8][8];
    #pragma unroll
    for (int i = 0; i < 8; i++)
        #pragma unroll
        for (int j = 0; j < 8; j++) acc[i][j] = 0.0f;

    for (int kt = 0; kt < K; kt += BK) {
        // Load A tile: 128x16 floats = 512 float4, 2 per thread, store transposed
        #pragma unroll
        for (int l = 0; l < 2; l++) {
            int linv = tid + l * 256;       // 0..511
            int r    = linv >> 2;           // row in tile 0..127
            int c4   = linv & 3;            // which float4 along K
            float4 v = *reinterpret_cast<const float4*>(Ablk + (size_t)r * K + kt + c4 * 4);
            As[c4 * 4 + 0][r] = v.x;
            As[c4 * 4 + 1][r] = v.y;
            As[c4 * 4 + 2][r] = v.z;
            As[c4 * 4 + 3][r] = v.w;
        }
        // Load B tile: 16x128 floats = 512 float4, 2 per thread, direct
        #pragma unroll
        for (int l = 0; l < 2; l++) {
            int linv = tid + l * 256;
            int kr   = linv >> 5;           // 0..15
            int c4   = linv & 31;           // float4 along N
            *reinterpret_cast<float4*>(&Bs[kr][c4 * 4]) =
                *reinterpret_cast<const float4*>(Bblk + (size_t)(kt + kr) * N + c4 * 4);
        }
        __syncthreads();

        #pragma unroll
        for (int kk = 0; kk < BK; kk++) {
            float a[8], b[8];
            #pragma unroll
            for (int i = 0; i < 8; i++) a[i] = As[kk][tm * 8 + i];
            #pragma unroll
            for (int j = 0; j < 8; j++) b[j] = Bs[kk][tn * 8 + j];
            #pragma unroll
            for (int i = 0; i < 8; i++)
                #pragma unroll
                for (int j = 0; j < 8; j++)
                    acc[i][j] = fmaf(a[i], b[j], acc[i][j]);
        }
        __syncthreads();
    }

    // Epilogue
    #pragma unroll
    for (int i = 0; i < 8; i++) {
        int row = bm * BM + tm * 8 + i;
        #pragma unroll
        for (int j = 0; j < 8; j++) {
            int col = bn * BN + tn * 8 + j;
            float c = acc[i][j] + bias[col];
            float o;
            if (EPI == 0) { float rv = fmaxf(c, 0.0f); o = rv * rv; }
            else if (EPI == 1) { o = 1.0f / (1.0f + expf(-c)); }
            else { o = c * aux[(size_t)row * N + col]; }
            C[(size_t)row * N + col] = o;
        }
    }
}

// ---------------------------------------------------------------------------
// Launch: shift -> k = relu(xk@Wk+bk)^2 -> s = sigmoid(xr@Wr+br) -> out = (k@Wv+bv)*s
// ---------------------------------------------------------------------------
extern "C" void kernel_launch(void* const* d_in, const int* in_sizes, int n_in,
                              void* d_out, int out_size) {
    const float* x   = (const float*)d_in[0];
    const int*   pos = (const int*)  d_in[1];
    const float* tmk = (const float*)d_in[2];
    const float* tmr = (const float*)d_in[3];
    const float* Wk  = (const float*)d_in[4];
    const float* bk  = (const float*)d_in[5];
    const float* Wv  = (const float*)d_in[6];
    const float* bv  = (const float*)d_in[7];
    const float* Wr  = (const float*)d_in[8];
    const float* br  = (const float*)d_in[9];
    float* out = (float*)d_out;

    // Symbol address lookups are pure (no stream ops) -> graph-capture safe.
    void *p_xk, *p_xr, *p_k, *p_s;
    cudaGetSymbolAddress(&p_xk, g_xk);
    cudaGetSymbolAddress(&p_xr, g_xr);
    cudaGetSymbolAddress(&p_k,  g_k);
    cudaGetSymbolAddress(&p_s,  g_s);
    float* xk   = (float*)p_xk;
    float* xr   = (float*)p_xr;
    float* kbuf = (float*)p_k;
    float* sbuf = (float*)p_s;

    // 1) token shift + mix
    shift_kernel<<<(TT * HH + 255) / 256, 256>>>(x, pos, tmk, tmr);

    // 2) k = relu(xk @ Wk + bk)^2     [8192 x 8192]
    {
        dim3 grid(II / 128, TT / 128);
        sgemm_kernel<0><<<grid, 256>>>(xk, Wk, bk, nullptr, kbuf, TT, II, HH);
    }
    // 3) s = sigmoid(xr @ Wr + br)    [8192 x 2048]
    {
        dim3 grid(HH / 128, TT / 128);
        sgemm_kernel<1><<<grid, 256>>>(xr, Wr, br, nullptr, sbuf, TT, HH, HH);
    }
    // 4) out = (k @ Wv + bv) * s      [8192 x 2048]
    {
        dim3 grid(HH / 128, TT / 128);
        sgemm_kernel<2><<<grid, 256>>>(kbuf, Wv, bv, sbuf, out, TT, HH, II);
    }
}

// round 11
// speedup vs baseline: 2.3989x; 2.3989x over previous
#include <cuda_runtime.h>
#include <cuda_bf16.h>
#include <cstdint>
#include <math.h>

#define TT 8192
#define HH 2048
#define II 8192

// ---------------- static device scratch (allocation-free rule) ----------------
__device__ __nv_bfloat16 g_xk_hi[TT * HH];
__device__ __nv_bfloat16 g_xk_lo[TT * HH];
__device__ __nv_bfloat16 g_xr_hi[TT * HH];
__device__ __nv_bfloat16 g_xr_lo[TT * HH];
__device__ __nv_bfloat16 g_wkT_hi[(size_t)II * HH];
__device__ __nv_bfloat16 g_wkT_lo[(size_t)II * HH];
__device__ __nv_bfloat16 g_wvT_hi[(size_t)HH * II];
__device__ __nv_bfloat16 g_wvT_lo[(size_t)HH * II];
__device__ __nv_bfloat16 g_wrT_hi[HH * HH];
__device__ __nv_bfloat16 g_wrT_lo[HH * HH];
__device__ __nv_bfloat16 g_k_hi[(size_t)TT * II];
__device__ __nv_bfloat16 g_k_lo[(size_t)TT * II];
__device__ float         g_s[TT * HH];

// ---------------- helpers (all base-target PTX: no 'a'-gated instructions) ----------------
__device__ __forceinline__ uint32_t smem_to_u32(const void* p) {
    uint32_t a;
    asm("{ .reg .u64 t; cvta.to.shared.u64 t, %1; cvt.u32.u64 %0, t; }" : "=r"(a) : "l"(p));
    return a;
}
__device__ __forceinline__ void cp16(uint32_t saddr, const void* gptr) {
    asm volatile("cp.async.cg.shared.global [%0], [%1], 16;" :: "r"(saddr), "l"(gptr));
}
__device__ __forceinline__ void cp_commit() {
    asm volatile("cp.async.commit_group;" ::: "memory");
}
__device__ __forceinline__ void ldsm_x4(uint32_t* r, uint32_t addr) {
    asm volatile("ldmatrix.sync.aligned.m8n8.x4.shared.b16 {%0,%1,%2,%3}, [%4];"
                 : "=r"(r[0]), "=r"(r[1]), "=r"(r[2]), "=r"(r[3]) : "r"(addr));
}
__device__ __forceinline__ void ldsm_x2(uint32_t* r, uint32_t addr) {
    asm volatile("ldmatrix.sync.aligned.m8n8.x2.shared.b16 {%0,%1}, [%2];"
                 : "=r"(r[0]), "=r"(r[1]) : "r"(addr));
}
__device__ __forceinline__ void mma16816(float* c, const uint32_t* a, const uint32_t* b) {
    asm volatile("mma.sync.aligned.m16n8k16.row.col.f32.bf16.bf16.f32 "
                 "{%0,%1,%2,%3}, {%4,%5,%6,%7}, {%8,%9}, {%0,%1,%2,%3};"
                 : "+f"(c[0]), "+f"(c[1]), "+f"(c[2]), "+f"(c[3])
                 : "r"(a[0]), "r"(a[1]), "r"(a[2]), "r"(a[3]), "r"(b[0]), "r"(b[1]));
}

// ---------------- prep kernels ----------------
__global__ void shift_convert_kernel(const float* __restrict__ x,
                                     const int* __restrict__ pos,
                                     const float* __restrict__ tmk,
                                     const float* __restrict__ tmr) {
    int idx = blockIdx.x * blockDim.x + threadIdx.x;
    if (idx >= TT * HH) return;
    int t = idx >> 11;
    int h = idx & (HH - 1);
    float xv = x[idx];
    float st = (pos[t] == 0) ? 0.0f : x[idx - HH];
    float mk = tmk[h], mr = tmr[h];
    float xk = xv * mk + st * (1.0f - mk);
    float xr = xv * mr + st * (1.0f - mr);
    __nv_bfloat16 h1 = __float2bfloat16(xk);
    g_xk_hi[idx] = h1;
    g_xk_lo[idx] = __float2bfloat16(xk - __bfloat162float(h1));
    __nv_bfloat16 h2 = __float2bfloat16(xr);
    g_xr_hi[idx] = h2;
    g_xr_lo[idx] = __float2bfloat16(xr - __bfloat162float(h2));
}

// W[R,C] row-major -> out[C,R] bf16 hi/lo
__global__ void transpose_convert_kernel(const float* __restrict__ W,
                                         __nv_bfloat16* __restrict__ oh,
                                         __nv_bfloat16* __restrict__ ol,
                                         int R, int C) {
    __shared__ float tile[32][33];
    int c0 = blockIdx.x * 32, r0 = blockIdx.y * 32;
    int tx = threadIdx.x, ty = threadIdx.y;
    #pragma unroll
    for (int i = ty; i < 32; i += 8)
        tile[i][tx] = W[(size_t)(r0 + i) * C + c0 + tx];
    __syncthreads();
    #pragma unroll
    for (int i = ty; i < 32; i += 8) {
        float v = tile[tx][i];               // W[r0+tx][c0+i]
        size_t o = (size_t)(c0 + i) * R + r0 + tx;
        __nv_bfloat16 hv = __float2bfloat16(v);
        oh[o] = hv;
        ol[o] = __float2bfloat16(v - __bfloat162float(hv));
    }
}

// ---------------- HMMA GEMM: C[M,Ntot] = epi(A[M,K] x (B[Ntot,K])^T + bias) ----------------
// 3-product bf16 split: Ahi*Bhi + Alo*Bhi + Ahi*Blo, fp32 accum.
// CTA tile 128x128, BK=32, 8 warps (2 M x 4 N), warp tile 64x32.
// smem: padded rows (80B stride) -> conflict-free ldmatrix; cp.async double buffer.
static constexpr int STRIDE  = 80;            // bytes per 32-elem bf16 row (padded)
static constexpr int MATB    = 128 * STRIDE;  // 10240 B per tile matrix
static constexpr int BUFB    = 4 * MATB;      // Ahi,Alo,Bhi,Blo
static constexpr int SMEMB   = 2 * BUFB;      // double buffer = 81920

template <int EPI>
__global__ __launch_bounds__(256, 2)
void gemm_hmma(const __nv_bfloat16* __restrict__ Ahi, const __nv_bfloat16* __restrict__ Alo,
               const __nv_bfloat16* __restrict__ Bhi, const __nv_bfloat16* __restrict__ Blo,
               const float* __restrict__ bias, const float* __restrict__ aux,
               float* __restrict__ outF,
               __nv_bfloat16* __restrict__ outHi, __nv_bfloat16* __restrict__ outLo,
               int K, int Ntot) {
    extern __shared__ char smem[];
    const uint32_t smbase = smem_to_u32(smem);
    const int tid  = threadIdx.x;
    const int lane = tid & 31;
    const int wid  = tid >> 5;
    const int warp_m = wid & 1;   // 0..1 -> 64 rows each
    const int warp_n = wid >> 1;  // 0..3 -> 32 cols each
    const int bm = blockIdx.y, bn = blockIdx.x;

    float acc[4][4][4];
    #pragma unroll
    for (int i = 0; i < 4; i++)
        #pragma unroll
        for (int j = 0; j < 4; j++)
            #pragma unroll
            for (int q = 0; q < 4; q++) acc[i][j][q] = 0.0f;

    // per-thread load slots: 2 chunks (16B) per matrix per thread
    const int c0 = tid, c1 = tid + 256;          // chunk ids 0..511
    const int r0c = c0 >> 2, k0c = c0 & 3;
    const int r1c = c1 >> 2, k1c = c1 & 3;

    const int niter = K >> 5;                    // BK=32

    // ldmatrix lane addressing
    const int lg = lane >> 3, lr = lane & 7;
    // A x4: row += (lg&1)*8, col16B += (lg>>1)
    const uint32_t a_row_off = (uint32_t)(warp_m * 64 + (lg & 1) * 8 + lr) * STRIDE + (uint32_t)(lg >> 1) * 16;
    // B x2: row = warp_n*32 + nt*8 + lr, col16B += (lg&1)
    const uint32_t b_row_off = (uint32_t)(warp_n * 32 + lr) * STRIDE + (uint32_t)(lg & 1) * 16;

    // prologue: tile 0 -> buf 0
    {
        const int kt = 0;
        #pragma unroll
        for (int s = 0; s < 2; s++) {
            int row = s ? r1c : r0c, kc = s ? k1c : k0c;
            uint32_t so = (uint32_t)row * STRIDE + kc * 16;
            size_t gA = (size_t)(bm * 128 + row) * K + kt + kc * 8;
            size_t gB = (size_t)(bn * 128 + row) * K + kt + kc * 8;
            cp16(smbase + 0 * MATB + so, Ahi + gA);
            cp16(smbase + 1 * MATB + so, Alo + gA);
            cp16(smbase + 2 * MATB + so, Bhi + gB);
            cp16(smbase + 3 * MATB + so, Blo + gB);
        }
        cp_commit();
    }

    for (int it = 0; it < niter; it++) {
        const int b = it & 1;
        if (it + 1 < niter) {
            const int kt = (it + 1) << 5;
            const uint32_t base = smbase + (b ^ 1) * BUFB;
            #pragma unroll
            for (int s = 0; s < 2; s++) {
                int row = s ? r1c : r0c, kc = s ? k1c : k0c;
                uint32_t so = (uint32_t)row * STRIDE + kc * 16;
                size_t gA = (size_t)(bm * 128 + row) * K + kt + kc * 8;
                size_t gB = (size_t)(bn * 128 + row) * K + kt + kc * 8;
                cp16(base + 0 * MATB + so, Ahi + gA);
                cp16(base + 1 * MATB + so, Alo + gA);
                cp16(base + 2 * MATB + so, Bhi + gB);
                cp16(base + 3 * MATB + so, Blo + gB);
            }
            cp_commit();
            asm volatile("cp.async.wait_group 1;" ::: "memory");
        } else {
            asm volatile("cp.async.wait_group 0;" ::: "memory");
        }
        __syncthreads();

        const uint32_t bufb = smbase + b * BUFB;
        #pragma unroll
        for (int p = 0; p < 3; p++) {
            const uint32_t aBase = bufb + (p == 1 ? MATB : 0);
            const uint32_t bBase = bufb + (p == 2 ? 3 * MATB : 2 * MATB);
            #pragma unroll
            for (int ks = 0; ks < 2; ks++) {   // k offset 0 / 16 elems = 0 / 32 bytes
                uint32_t afr[4][4], bfr[4][2];
                #pragma unroll
                for (int mt = 0; mt < 4; mt++)
                    ldsm_x4(afr[mt], aBase + a_row_off + (uint32_t)mt * 16 * STRIDE + ks * 32);
                #pragma unroll
                for (int nt = 0; nt < 4; nt++)
                    ldsm_x2(bfr[nt], bBase + b_row_off + (uint32_t)nt * 8 * STRIDE + ks * 32);
                #pragma unroll
                for (int mt = 0; mt < 4; mt++)
                    #pragma unroll
                    for (int nt = 0; nt < 4; nt++)
                        mma16816(acc[mt][nt], afr[mt], bfr[nt]);
            }
        }
        __syncthreads();
    }

    // ---- epilogue: fragment c -> gmem ----
    const int erow = lane >> 2;          // 0..7
    const int ecol = (lane & 3) * 2;     // 0,2,4,6
    #pragma unroll
    for (int mt = 0; mt < 4; mt++) {
        const int rbase = bm * 128 + warp_m * 64 + mt * 16 + erow;
        #pragma unroll
        for (int nt = 0; nt < 4; nt++) {
            const int col = bn * 128 + warp_n * 32 + nt * 8 + ecol;
            const float b0 = bias[col], b1 = bias[col + 1];
            #pragma unroll
            for (int half = 0; half < 2; half++) {   // c0,c1 then c2,c3 (row +8)
                const int row = rbase + half * 8;
                const float v0 = acc[mt][nt][half * 2 + 0] + b0;
                const float v1 = acc[mt][nt][half * 2 + 1] + b1;
                const size_t o = (size_t)row * Ntot + col;
                if (EPI == 0) {
                    float r0v = fmaxf(v0, 0.0f), r1v = fmaxf(v1, 0.0f);
                    float s0 = r0v * r0v, s1 = r1v * r1v;
                    __nv_bfloat16 h0 = __float2bfloat16(s0), h1 = __float2bfloat16(s1);
                    __nv_bfloat16 l0 = __float2bfloat16(s0 - __bfloat162float(h0));
                    __nv_bfloat16 l1 = __float2bfloat16(s1 - __bfloat162float(h1));
                    *reinterpret_cast<__nv_bfloat162*>(outHi + o) = __nv_bfloat162(h0, h1);
                    *reinterpret_cast<__nv_bfloat162*>(outLo + o) = __nv_bfloat162(l0, l1);
                } else if (EPI == 1) {
                    float2 v;
                    v.x = 1.0f / (1.0f + expf(-v0));
                    v.y = 1.0f / (1.0f + expf(-v1));
                    *reinterpret_cast<float2*>(outF + o) = v;
                } else {
                    float2 sv = *reinterpret_cast<const float2*>(aux + o);
                    float2 v;
                    v.x = v0 * sv.x;
                    v.y = v1 * sv.y;
                    *reinterpret_cast<float2*>(outF + o) = v;
                }
            }
        }
    }
}

// ---------------- launch ----------------
extern "C" void kernel_launch(void* const* d_in, const int* in_sizes, int n_in,
                              void* d_out, int out_size) {
    const float* x   = (const float*)d_in[0];
    const int*   pos = (const int*)  d_in[1];
    const float* tmk = (const float*)d_in[2];
    const float* tmr = (const float*)d_in[3];
    const float* Wk  = (const float*)d_in[4];
    const float* bk  = (const float*)d_in[5];
    const float* Wv  = (const float*)d_in[6];
    const float* bv  = (const float*)d_in[7];
    const float* Wr  = (const float*)d_in[8];
    const float* br  = (const float*)d_in[9];
    float* out = (float*)d_out;

    void* p;
    cudaGetSymbolAddress(&p, g_xk_hi); __nv_bfloat16* xk_hi = (__nv_bfloat16*)p;
    cudaGetSymbolAddress(&p, g_xk_lo); __nv_bfloat16* xk_lo = (__nv_bfloat16*)p;
    cudaGetSymbolAddress(&p, g_xr_hi); __nv_bfloat16* xr_hi = (__nv_bfloat16*)p;
    cudaGetSymbolAddress(&p, g_xr_lo); __nv_bfloat16* xr_lo = (__nv_bfloat16*)p;
    cudaGetSymbolAddress(&p, g_wkT_hi); __nv_bfloat16* wkT_hi = (__nv_bfloat16*)p;
    cudaGetSymbolAddress(&p, g_wkT_lo); __nv_bfloat16* wkT_lo = (__nv_bfloat16*)p;
    cudaGetSymbolAddress(&p, g_wvT_hi); __nv_bfloat16* wvT_hi = (__nv_bfloat16*)p;
    cudaGetSymbolAddress(&p, g_wvT_lo); __nv_bfloat16* wvT_lo = (__nv_bfloat16*)p;
    cudaGetSymbolAddress(&p, g_wrT_hi); __nv_bfloat16* wrT_hi = (__nv_bfloat16*)p;
    cudaGetSymbolAddress(&p, g_wrT_lo); __nv_bfloat16* wrT_lo = (__nv_bfloat16*)p;
    cudaGetSymbolAddress(&p, g_k_hi);   __nv_bfloat16* k_hi   = (__nv_bfloat16*)p;
    cudaGetSymbolAddress(&p, g_k_lo);   __nv_bfloat16* k_lo   = (__nv_bfloat16*)p;
    cudaGetSymbolAddress(&p, g_s);      float* sbuf = (float*)p;

    cudaFuncSetAttribute(gemm_hmma<0>, cudaFuncAttributeMaxDynamicSharedMemorySize, SMEMB);
    cudaFuncSetAttribute(gemm_hmma<1>, cudaFuncAttributeMaxDynamicSharedMemorySize, SMEMB);
    cudaFuncSetAttribute(gemm_hmma<2>, cudaFuncAttributeMaxDynamicSharedMemorySize, SMEMB);

    // 1) shift + mix + bf16 split
    shift_convert_kernel<<<(TT * HH + 255) / 256, 256>>>(x, pos, tmk, tmr);

    // 2) weight transpose + split
    {
        dim3 blk(32, 8);
        transpose_convert_kernel<<<dim3(II / 32, HH / 32), blk>>>(Wk, wkT_hi, wkT_lo, HH, II);
        transpose_convert_kernel<<<dim3(HH / 32, II / 32), blk>>>(Wv, wvT_hi, wvT_lo, II, HH);
        transpose_convert_kernel<<<dim3(HH / 32, HH / 32), blk>>>(Wr, wrT_hi, wrT_lo, HH, HH);
    }

    // 3) k = relu(xk @ Wk + bk)^2 -> bf16 hi/lo    [8192 x 8192], K=2048
    gemm_hmma<0><<<dim3(II / 128, TT / 128), 256, SMEMB>>>(
        xk_hi, xk_lo, wkT_hi, wkT_lo, bk, nullptr, nullptr, k_hi, k_lo, HH, II);

    // 4) s = sigmoid(xr @ Wr + br)                 [8192 x 2048], K=2048
    gemm_hmma<1><<<dim3(HH / 128, TT / 128), 256, SMEMB>>>(
        xr_hi, xr_lo, wrT_hi, wrT_lo, br, nullptr, sbuf, nullptr, nullptr, HH, HH);

    // 5) out = (k @ Wv + bv) * s                   [8192 x 2048], K=8192
    gemm_hmma<2><<<dim3(HH / 128, TT / 128), 256, SMEMB>>>(
        k_hi, k_lo, wvT_hi, wvT_lo, bv, sbuf, out, nullptr, nullptr, II, HH);
}

// round 15
// speedup vs baseline: 2.6503x; 1.1048x over previous
#include <cuda_runtime.h>
#include <cuda_bf16.h>
#include <cstdint>
#include <math.h>

#define TT 8192
#define HH 2048
#define II 8192

// ---------------- static device scratch (allocation-free rule) ----------------
__device__ __nv_bfloat16 g_xk_hi[TT * HH];
__device__ __nv_bfloat16 g_xk_lo[TT * HH];
__device__ __nv_bfloat16 g_xr_hi[TT * HH];
__device__ __nv_bfloat16 g_xr_lo[TT * HH];
__device__ __nv_bfloat16 g_wkT_hi[(size_t)II * HH];
__device__ __nv_bfloat16 g_wkT_lo[(size_t)II * HH];
__device__ __nv_bfloat16 g_wvT_hi[(size_t)HH * II];
__device__ __nv_bfloat16 g_wvT_lo[(size_t)HH * II];
__device__ __nv_bfloat16 g_wrT_hi[HH * HH];
__device__ __nv_bfloat16 g_wrT_lo[HH * HH];
__device__ __nv_bfloat16 g_k_hi[(size_t)TT * II];
__device__ __nv_bfloat16 g_k_lo[(size_t)TT * II];
__device__ float         g_s[TT * HH];

// ---------------- helpers (all base-target PTX: no 'a'-gated instructions) ----------------
__device__ __forceinline__ uint32_t smem_to_u32(const void* p) {
    uint32_t a;
    asm("{ .reg .u64 t; cvta.to.shared.u64 t, %1; cvt.u32.u64 %0, t; }" : "=r"(a) : "l"(p));
    return a;
}
__device__ __forceinline__ void cp16(uint32_t saddr, const void* gptr) {
    asm volatile("cp.async.cg.shared.global [%0], [%1], 16;" :: "r"(saddr), "l"(gptr));
}
__device__ __forceinline__ void cp_commit() {
    asm volatile("cp.async.commit_group;" ::: "memory");
}
__device__ __forceinline__ void ldsm_x4(uint32_t* r, uint32_t addr) {
    asm volatile("ldmatrix.sync.aligned.m8n8.x4.shared.b16 {%0,%1,%2,%3}, [%4];"
                 : "=r"(r[0]), "=r"(r[1]), "=r"(r[2]), "=r"(r[3]) : "r"(addr));
}
__device__ __forceinline__ void mma16816(float* c, const uint32_t* a, const uint32_t* b) {
    asm volatile("mma.sync.aligned.m16n8k16.row.col.f32.bf16.bf16.f32 "
                 "{%0,%1,%2,%3}, {%4,%5,%6,%7}, {%8,%9}, {%0,%1,%2,%3};"
                 : "+f"(c[0]), "+f"(c[1]), "+f"(c[2]), "+f"(c[3])
                 : "r"(a[0]), "r"(a[1]), "r"(a[2]), "r"(a[3]), "r"(b[0]), "r"(b[1]));
}

// ---------------- prep kernels ----------------
__global__ void shift_convert_kernel(const float* __restrict__ x,
                                     const int* __restrict__ pos,
                                     const float* __restrict__ tmk,
                                     const float* __restrict__ tmr) {
    int idx = blockIdx.x * blockDim.x + threadIdx.x;
    if (idx >= TT * HH) return;
    int t = idx >> 11;
    int h = idx & (HH - 1);
    float xv = x[idx];
    float st = (pos[t] == 0) ? 0.0f : x[idx - HH];
    float mk = tmk[h], mr = tmr[h];
    float xk = xv * mk + st * (1.0f - mk);
    float xr = xv * mr + st * (1.0f - mr);
    __nv_bfloat16 h1 = __float2bfloat16(xk);
    g_xk_hi[idx] = h1;
    g_xk_lo[idx] = __float2bfloat16(xk - __bfloat162float(h1));
    __nv_bfloat16 h2 = __float2bfloat16(xr);
    g_xr_hi[idx] = h2;
    g_xr_lo[idx] = __float2bfloat16(xr - __bfloat162float(h2));
}

// W[R,C] row-major -> out[C,R] bf16 hi/lo
__global__ void transpose_convert_kernel(const float* __restrict__ W,
                                         __nv_bfloat16* __restrict__ oh,
                                         __nv_bfloat16* __restrict__ ol,
                                         int R, int C) {
    __shared__ float tile[32][33];
    int c0 = blockIdx.x * 32, r0 = blockIdx.y * 32;
    int tx = threadIdx.x, ty = threadIdx.y;
    #pragma unroll
    for (int i = ty; i < 32; i += 8)
        tile[i][tx] = W[(size_t)(r0 + i) * C + c0 + tx];
    __syncthreads();
    #pragma unroll
    for (int i = ty; i < 32; i += 8) {
        float v = tile[tx][i];               // W[r0+tx][c0+i]
        size_t o = (size_t)(c0 + i) * R + r0 + tx;
        __nv_bfloat16 hv = __float2bfloat16(v);
        oh[o] = hv;
        ol[o] = __float2bfloat16(v - __bfloat162float(hv));
    }
}

// ---------------- HMMA GEMM: C[M,Ntot] = epi(A[M,K] x (B[Ntot,K])^T + bias) ----------------
// 3-product bf16 split with FRAGMENT REUSE: load Ahi/Bhi/Blo once per k-step,
// run hi*hi and hi*lo; then load Alo (Ahi dead) and run lo*hi.
// CTA tile 128x128, BK=32, 8 warps (2 M x 4 N), warp tile 64x32.
static constexpr int STRIDE  = 80;            // bytes per 32-elem bf16 row (padded)
static constexpr int MATB    = 128 * STRIDE;  // 10240 B per tile matrix
static constexpr int BUFB    = 4 * MATB;      // Ahi,Alo,Bhi,Blo
static constexpr int SMEMB   = 2 * BUFB;      // double buffer = 81920

template <int EPI>
__global__ __launch_bounds__(256, 2)
void gemm_hmma(const __nv_bfloat16* __restrict__ Ahi, const __nv_bfloat16* __restrict__ Alo,
               const __nv_bfloat16* __restrict__ Bhi, const __nv_bfloat16* __restrict__ Blo,
               const float* __restrict__ bias, const float* __restrict__ aux,
               float* __restrict__ outF,
               __nv_bfloat16* __restrict__ outHi, __nv_bfloat16* __restrict__ outLo,
               int K, int Ntot) {
    extern __shared__ char smem[];
    const uint32_t smbase = smem_to_u32(smem);
    const int tid  = threadIdx.x;
    const int lane = tid & 31;
    const int wid  = tid >> 5;
    const int warp_m = wid & 1;   // 0..1 -> 64 rows each
    const int warp_n = wid >> 1;  // 0..3 -> 32 cols each
    const int bm = blockIdx.y, bn = blockIdx.x;

    float acc[4][4][4];
    #pragma unroll
    for (int i = 0; i < 4; i++)
        #pragma unroll
        for (int j = 0; j < 4; j++)
            #pragma unroll
            for (int q = 0; q < 4; q++) acc[i][j][q] = 0.0f;

    // per-thread load slots: 2 chunks (16B) per matrix per thread
    const int c0 = tid, c1 = tid + 256;          // chunk ids 0..511
    const int r0c = c0 >> 2, k0c = c0 & 3;
    const int r1c = c1 >> 2, k1c = c1 & 3;

    const int niter = K >> 5;                    // BK=32

    // ldmatrix lane addressing
    const int lg = lane >> 3, lr = lane & 7;
    // A x4 (m16 x k16): matrices = {r0-7/k0, r8-15/k0, r0-7/k1, r8-15/k1}
    const uint32_t a_row_off = (uint32_t)(warp_m * 64 + (lg & 1) * 8 + lr) * STRIDE + (uint32_t)(lg >> 1) * 16;
    // B x4 (2 n-tiles x k16): matrices = {nt/k0, nt/k1, nt+1/k0, nt+1/k1}
    const uint32_t b4_off = (uint32_t)(warp_n * 32 + (lg >> 1) * 8 + lr) * STRIDE + (uint32_t)(lg & 1) * 16;

    // prologue: tile 0 -> buf 0
    {
        const int kt = 0;
        #pragma unroll
        for (int s = 0; s < 2; s++) {
            int row = s ? r1c : r0c, kc = s ? k1c : k0c;
            uint32_t so = (uint32_t)row * STRIDE + kc * 16;
            size_t gA = (size_t)(bm * 128 + row) * K + kt + kc * 8;
            size_t gB = (size_t)(bn * 128 + row) * K + kt + kc * 8;
            cp16(smbase + 0 * MATB + so, Ahi + gA);
            cp16(smbase + 1 * MATB + so, Alo + gA);
            cp16(smbase + 2 * MATB + so, Bhi + gB);
            cp16(smbase + 3 * MATB + so, Blo + gB);
        }
        cp_commit();
    }

    for (int it = 0; it < niter; it++) {
        const int b = it & 1;
        if (it + 1 < niter) {
            const int kt = (it + 1) << 5;
            const uint32_t base = smbase + (b ^ 1) * BUFB;
            #pragma unroll
            for (int s = 0; s < 2; s++) {
                int row = s ? r1c : r0c, kc = s ? k1c : k0c;
                uint32_t so = (uint32_t)row * STRIDE + kc * 16;
                size_t gA = (size_t)(bm * 128 + row) * K + kt + kc * 8;
                size_t gB = (size_t)(bn * 128 + row) * K + kt + kc * 8;
                cp16(base + 0 * MATB + so, Ahi + gA);
                cp16(base + 1 * MATB + so, Alo + gA);
                cp16(base + 2 * MATB + so, Bhi + gB);
                cp16(base + 3 * MATB + so, Blo + gB);
            }
            cp_commit();
            asm volatile("cp.async.wait_group 1;" ::: "memory");
        } else {
            asm volatile("cp.async.wait_group 0;" ::: "memory");
        }
        __syncthreads();

        const uint32_t bufb = smbase + b * BUFB;
        #pragma unroll
        for (int ks = 0; ks < 2; ks++) {   // k offset 0 / 16 elems = 0 / 32 bytes
            uint32_t ah[4][4], bh[2][4], bl[2][4];
            #pragma unroll
            for (int mt = 0; mt < 4; mt++)
                ldsm_x4(ah[mt], bufb + 0 * MATB + a_row_off + (uint32_t)mt * 16 * STRIDE + ks * 32);
            #pragma unroll
            for (int np = 0; np < 2; np++) {
                ldsm_x4(bh[np], bufb + 2 * MATB + b4_off + (uint32_t)np * 16 * STRIDE + ks * 32);
                ldsm_x4(bl[np], bufb + 3 * MATB + b4_off + (uint32_t)np * 16 * STRIDE + ks * 32);
            }
            // products hi*hi and hi*lo (Ahi live)
            #pragma unroll
            for (int mt = 0; mt < 4; mt++)
                #pragma unroll
                for (int nt = 0; nt < 4; nt++) {
                    mma16816(acc[mt][nt], ah[mt], &bh[nt >> 1][(nt & 1) * 2]);
                    mma16816(acc[mt][nt], ah[mt], &bl[nt >> 1][(nt & 1) * 2]);
                }
            // product lo*hi (reload A as Alo; Ahi dead)
            uint32_t al[4][4];
            #pragma unroll
            for (int mt = 0; mt < 4; mt++)
                ldsm_x4(al[mt], bufb + 1 * MATB + a_row_off + (uint32_t)mt * 16 * STRIDE + ks * 32);
            #pragma unroll
            for (int mt = 0; mt < 4; mt++)
                #pragma unroll
                for (int nt = 0; nt < 4; nt++)
                    mma16816(acc[mt][nt], al[mt], &bh[nt >> 1][(nt & 1) * 2]);
        }
        __syncthreads();
    }

    // ---- epilogue: fragment c -> gmem ----
    const int erow = lane >> 2;          // 0..7
    const int ecol = (lane & 3) * 2;     // 0,2,4,6
    #pragma unroll
    for (int mt = 0; mt < 4; mt++) {
        const int rbase = bm * 128 + warp_m * 64 + mt * 16 + erow;
        #pragma unroll
        for (int nt = 0; nt < 4; nt++) {
            const int col = bn * 128 + warp_n * 32 + nt * 8 + ecol;
            const float b0 = bias[col], b1 = bias[col + 1];
            #pragma unroll
            for (int half = 0; half < 2; half++) {   // c0,c1 then c2,c3 (row +8)
                const int row = rbase + half * 8;
                const float v0 = acc[mt][nt][half * 2 + 0] + b0;
                const float v1 = acc[mt][nt][half * 2 + 1] + b1;
                const size_t o = (size_t)row * Ntot + col;
                if (EPI == 0) {
                    float r0v = fmaxf(v0, 0.0f), r1v = fmaxf(v1, 0.0f);
                    float s0 = r0v * r0v, s1 = r1v * r1v;
                    __nv_bfloat16 h0 = __float2bfloat16(s0), h1 = __float2bfloat16(s1);
                    __nv_bfloat16 l0 = __float2bfloat16(s0 - __bfloat162float(h0));
                    __nv_bfloat16 l1 = __float2bfloat16(s1 - __bfloat162float(h1));
                    *reinterpret_cast<__nv_bfloat162*>(outHi + o) = __nv_bfloat162(h0, h1);
                    *reinterpret_cast<__nv_bfloat162*>(outLo + o) = __nv_bfloat162(l0, l1);
                } else if (EPI == 1) {
                    float2 v;
                    v.x = 1.0f / (1.0f + expf(-v0));
                    v.y = 1.0f / (1.0f + expf(-v1));
                    *reinterpret_cast<float2*>(outF + o) = v;
                } else {
                    float2 sv = *reinterpret_cast<const float2*>(aux + o);
                    float2 v;
                    v.x = v0 * sv.x;
                    v.y = v1 * sv.y;
                    *reinterpret_cast<float2*>(outF + o) = v;
                }
            }
        }
    }
}

// ---------------- launch ----------------
extern "C" void kernel_launch(void* const* d_in, const int* in_sizes, int n_in,
                              void* d_out, int out_size) {
    const float* x   = (const float*)d_in[0];
    const int*   pos = (const int*)  d_in[1];
    const float* tmk = (const float*)d_in[2];
    const float* tmr = (const float*)d_in[3];
    const float* Wk  = (const float*)d_in[4];
    const float* bk  = (const float*)d_in[5];
    const float* Wv  = (const float*)d_in[6];
    const float* bv  = (const float*)d_in[7];
    const float* Wr  = (const float*)d_in[8];
    const float* br  = (const float*)d_in[9];
    float* out = (float*)d_out;

    void* p;
    cudaGetSymbolAddress(&p, g_xk_hi); __nv_bfloat16* xk_hi = (__nv_bfloat16*)p;
    cudaGetSymbolAddress(&p, g_xk_lo); __nv_bfloat16* xk_lo = (__nv_bfloat16*)p;
    cudaGetSymbolAddress(&p, g_xr_hi); __nv_bfloat16* xr_hi = (__nv_bfloat16*)p;
    cudaGetSymbolAddress(&p, g_xr_lo); __nv_bfloat16* xr_lo = (__nv_bfloat16*)p;
    cudaGetSymbolAddress(&p, g_wkT_hi); __nv_bfloat16* wkT_hi = (__nv_bfloat16*)p;
    cudaGetSymbolAddress(&p, g_wkT_lo); __nv_bfloat16* wkT_lo = (__nv_bfloat16*)p;
    cudaGetSymbolAddress(&p, g_wvT_hi); __nv_bfloat16* wvT_hi = (__nv_bfloat16*)p;
    cudaGetSymbolAddress(&p, g_wvT_lo); __nv_bfloat16* wvT_lo = (__nv_bfloat16*)p;
    cudaGetSymbolAddress(&p, g_wrT_hi); __nv_bfloat16* wrT_hi = (__nv_bfloat16*)p;
    cudaGetSymbolAddress(&p, g_wrT_lo); __nv_bfloat16* wrT_lo = (__nv_bfloat16*)p;
    cudaGetSymbolAddress(&p, g_k_hi);   __nv_bfloat16* k_hi   = (__nv_bfloat16*)p;
    cudaGetSymbolAddress(&p, g_k_lo);   __nv_bfloat16* k_lo   = (__nv_bfloat16*)p;
    cudaGetSymbolAddress(&p, g_s);      float* sbuf = (float*)p;

    cudaFuncSetAttribute(gemm_hmma<0>, cudaFuncAttributeMaxDynamicSharedMemorySize, SMEMB);
    cudaFuncSetAttribute(gemm_hmma<1>, cudaFuncAttributeMaxDynamicSharedMemorySize, SMEMB);
    cudaFuncSetAttribute(gemm_hmma<2>, cudaFuncAttributeMaxDynamicSharedMemorySize, SMEMB);

    // 1) shift + mix + bf16 split
    shift_convert_kernel<<<(TT * HH + 255) / 256, 256>>>(x, pos, tmk, tmr);

    // 2) weight transpose + split
    {
        dim3 blk(32, 8);
        transpose_convert_kernel<<<dim3(II / 32, HH / 32), blk>>>(Wk, wkT_hi, wkT_lo, HH, II);
        transpose_convert_kernel<<<dim3(HH / 32, II / 32), blk>>>(Wv, wvT_hi, wvT_lo, II, HH);
        transpose_convert_kernel<<<dim3(HH / 32, HH / 32), blk>>>(Wr, wrT_hi, wrT_lo, HH, HH);
    }

    // 3) k = relu(xk @ Wk + bk)^2 -> bf16 hi/lo    [8192 x 8192], K=2048
    gemm_hmma<0><<<dim3(II / 128, TT / 128), 256, SMEMB>>>(
        xk_hi, xk_lo, wkT_hi, wkT_lo, bk, nullptr, nullptr, k_hi, k_lo, HH, II);

    // 4) s = sigmoid(xr @ Wr + br)                 [8192 x 2048], K=2048
    gemm_hmma<1><<<dim3(HH / 128, TT / 128), 256, SMEMB>>>(
        xr_hi, xr_lo, wrT_hi, wrT_lo, br, nullptr, sbuf, nullptr, nullptr, HH, HH);

    // 5) out = (k @ Wv + bv) * s                   [8192 x 2048], K=8192
    gemm_hmma<2><<<dim3(HH / 128, TT / 128), 256, SMEMB>>>(
        k_hi, k_lo, wvT_hi, wvT_lo, bv, sbuf, out, nullptr, nullptr, II, HH);
}